// round 1
// baseline (speedup 1.0000x reference)
#include <cuda_runtime.h>

#define NB 8
#define SQ 2048
#define SK 2048
#define DH 512

// scratch for ||k||^2 per (batch, key-row)
__device__ float g_ksq[NB * SK];

// ---------------------------------------------------------------------------
// Kernel 1: k_sq[b, k] = sum_d K[b,k,d]^2   (one warp per row)
// ---------------------------------------------------------------------------
__global__ __launch_bounds__(256) void ksq_kernel(const float* __restrict__ K) {
    int gw = (blockIdx.x * blockDim.x + threadIdx.x) >> 5;   // global warp = row
    int lane = threadIdx.x & 31;
    if (gw >= NB * SK) return;
    const float* row = K + (size_t)gw * DH;
    float s = 0.f;
    #pragma unroll
    for (int i = lane * 4; i < DH; i += 32 * 4) {
        float4 v = *(const float4*)(row + i);
        s = fmaf(v.x, v.x, s);
        s = fmaf(v.y, v.y, s);
        s = fmaf(v.z, v.z, s);
        s = fmaf(v.w, v.w, s);
    }
    #pragma unroll
    for (int o = 16; o > 0; o >>= 1) s += __shfl_xor_sync(0xffffffffu, s, o);
    if (lane == 0) g_ksq[gw] = s;
}

// ---------------------------------------------------------------------------
// Kernel 2: logits S[b,q,k] = (2*dot(Q[b,q,:], K[b,k,:]) - ksq[b,k]) / T
// NT SGEMM, 128x128 tile, BK=16, 256 threads, 8x8 per thread.
// ---------------------------------------------------------------------------
__global__ __launch_bounds__(256) void qk_kernel(const float* __restrict__ Q,
                                                 const float* __restrict__ Kk,
                                                 const float* __restrict__ temp,
                                                 float* __restrict__ S) {
    __shared__ float As[16][132];   // [k][m]
    __shared__ float Bs[16][132];   // [k][n]

    const int b  = blockIdx.z;
    const float* Qb = Q  + (size_t)b * SQ * DH;
    const float* Kb = Kk + (size_t)b * SK * DH;
    float*       Sb = S  + (size_t)b * SQ * SK;

    const int m0 = blockIdx.y * 128;
    const int n0 = blockIdx.x * 128;
    const int tid = threadIdx.x;

    const int lr = tid >> 2;          // 0..63  (load row group)
    const int lc = (tid & 3) << 2;    // 0,4,8,12
    const int tm = (tid >> 4) << 3;   // 0..120
    const int tn = (tid & 15) << 3;   // 0..120

    float acc[8][8];
    #pragma unroll
    for (int i = 0; i < 8; i++)
        #pragma unroll
        for (int j = 0; j < 8; j++) acc[i][j] = 0.f;

    for (int k0 = 0; k0 < DH; k0 += 16) {
        #pragma unroll
        for (int i = 0; i < 2; i++) {
            int row = lr + i * 64;
            float4 v = *(const float4*)(Qb + (size_t)(m0 + row) * DH + k0 + lc);
            As[lc + 0][row] = v.x; As[lc + 1][row] = v.y;
            As[lc + 2][row] = v.z; As[lc + 3][row] = v.w;
            float4 w = *(const float4*)(Kb + (size_t)(n0 + row) * DH + k0 + lc);
            Bs[lc + 0][row] = w.x; Bs[lc + 1][row] = w.y;
            Bs[lc + 2][row] = w.z; Bs[lc + 3][row] = w.w;
        }
        __syncthreads();
        #pragma unroll
        for (int kk = 0; kk < 16; kk++) {
            float a[8], bb[8];
            #pragma unroll
            for (int i = 0; i < 8; i++) a[i] = As[kk][tm + i];
            #pragma unroll
            for (int j = 0; j < 8; j++) bb[j] = Bs[kk][tn + j];
            #pragma unroll
            for (int i = 0; i < 8; i++)
                #pragma unroll
                for (int j = 0; j < 8; j++)
                    acc[i][j] = fmaf(a[i], bb[j], acc[i][j]);
        }
        __syncthreads();
    }

    const float invT = 1.0f / temp[0];
    float kq[8];
    #pragma unroll
    for (int j = 0; j < 8; j++) kq[j] = g_ksq[b * SK + n0 + tn + j];

    #pragma unroll
    for (int i = 0; i < 8; i++) {
        float* out = Sb + (size_t)(m0 + tm + i) * SK + n0 + tn;
        float4 r0, r1;
        r0.x = (2.0f * acc[i][0] - kq[0]) * invT;
        r0.y = (2.0f * acc[i][1] - kq[1]) * invT;
        r0.z = (2.0f * acc[i][2] - kq[2]) * invT;
        r0.w = (2.0f * acc[i][3] - kq[3]) * invT;
        r1.x = (2.0f * acc[i][4] - kq[4]) * invT;
        r1.y = (2.0f * acc[i][5] - kq[5]) * invT;
        r1.z = (2.0f * acc[i][6] - kq[6]) * invT;
        r1.w = (2.0f * acc[i][7] - kq[7]) * invT;
        *(float4*)(out + 0) = r0;
        *(float4*)(out + 4) = r1;
    }
}

// ---------------------------------------------------------------------------
// Kernel 3: in-place row softmax over SK=2048 (256 threads, 8 elems/thread)
// ---------------------------------------------------------------------------
__global__ __launch_bounds__(256) void softmax_kernel(float* __restrict__ W) {
    const int row = blockIdx.x;
    float* r = W + (size_t)row * SK;
    const int tid = threadIdx.x;

    float vals[8];
    float m = -3.0e38f;
    #pragma unroll
    for (int i = 0; i < 8; i++) {
        vals[i] = r[tid + i * 256];
        m = fmaxf(m, vals[i]);
    }

    __shared__ float red[8];
    #pragma unroll
    for (int o = 16; o > 0; o >>= 1) m = fmaxf(m, __shfl_xor_sync(0xffffffffu, m, o));
    if ((tid & 31) == 0) red[tid >> 5] = m;
    __syncthreads();
    m = red[0];
    #pragma unroll
    for (int w = 1; w < 8; w++) m = fmaxf(m, red[w]);
    __syncthreads();

    float s = 0.f;
    #pragma unroll
    for (int i = 0; i < 8; i++) {
        vals[i] = expf(vals[i] - m);
        s += vals[i];
    }
    #pragma unroll
    for (int o = 16; o > 0; o >>= 1) s += __shfl_xor_sync(0xffffffffu, s, o);
    if ((tid & 31) == 0) red[tid >> 5] = s;
    __syncthreads();
    s = red[0];
    #pragma unroll
    for (int w = 1; w < 8; w++) s += red[w];

    const float inv = 1.0f / s;
    #pragma unroll
    for (int i = 0; i < 8; i++) r[tid + i * 256] = vals[i] * inv;
}

// ---------------------------------------------------------------------------
// Kernel 4: O[b,q,d] = sum_k W[b,q,k] * V[b,k,d]
// NN SGEMM, 128x128 tile, BK=16, 256 threads, 8x8 per thread.
// ---------------------------------------------------------------------------
__global__ __launch_bounds__(256) void pv_kernel(const float* __restrict__ W,
                                                 const float* __restrict__ V,
                                                 float* __restrict__ O) {
    __shared__ float As[16][132];   // [k][m]  (W^T tile)
    __shared__ float Bs[16][132];   // [k][n]  (V tile)

    const int b  = blockIdx.z;
    const float* Wb = W + (size_t)b * SQ * SK;
    const float* Vb = V + (size_t)b * SK * DH;
    float*       Ob = O + (size_t)b * SQ * DH;

    const int m0 = blockIdx.y * 128;
    const int n0 = blockIdx.x * 128;
    const int tid = threadIdx.x;

    const int lr = tid >> 2;          // A load: 0..63
    const int lc = (tid & 3) << 2;
    const int br = tid >> 5;          // B load row: 0..7
    const int bc = (tid & 31) << 2;   // B load col: 0..124
    const int tm = (tid >> 4) << 3;
    const int tn = (tid & 15) << 3;

    float acc[8][8];
    #pragma unroll
    for (int i = 0; i < 8; i++)
        #pragma unroll
        for (int j = 0; j < 8; j++) acc[i][j] = 0.f;

    for (int k0 = 0; k0 < SK; k0 += 16) {
        #pragma unroll
        for (int i = 0; i < 2; i++) {
            int row = lr + i * 64;
            float4 v = *(const float4*)(Wb + (size_t)(m0 + row) * SK + k0 + lc);
            As[lc + 0][row] = v.x; As[lc + 1][row] = v.y;
            As[lc + 2][row] = v.z; As[lc + 3][row] = v.w;
        }
        #pragma unroll
        for (int i = 0; i < 2; i++) {
            int row = br + i * 8;
            float4 v = *(const float4*)(Vb + (size_t)(k0 + row) * DH + n0 + bc);
            *(float4*)&Bs[row][bc] = v;
        }
        __syncthreads();
        #pragma unroll
        for (int kk = 0; kk < 16; kk++) {
            float a[8], bb[8];
            #pragma unroll
            for (int i = 0; i < 8; i++) a[i] = As[kk][tm + i];
            #pragma unroll
            for (int j = 0; j < 8; j++) bb[j] = Bs[kk][tn + j];
            #pragma unroll
            for (int i = 0; i < 8; i++)
                #pragma unroll
                for (int j = 0; j < 8; j++)
                    acc[i][j] = fmaf(a[i], bb[j], acc[i][j]);
        }
        __syncthreads();
    }

    #pragma unroll
    for (int i = 0; i < 8; i++) {
        float* out = Ob + (size_t)(m0 + tm + i) * DH + n0 + tn;
        *(float4*)(out + 0) = make_float4(acc[i][0], acc[i][1], acc[i][2], acc[i][3]);
        *(float4*)(out + 4) = make_float4(acc[i][4], acc[i][5], acc[i][6], acc[i][7]);
    }
}

// ---------------------------------------------------------------------------
extern "C" void kernel_launch(void* const* d_in, const int* in_sizes, int n_in,
                              void* d_out, int out_size) {
    const float* Q = (const float*)d_in[0];
    const float* K = (const float*)d_in[1];
    const float* V = (const float*)d_in[2];
    const float* T = (const float*)d_in[3];

    float* attended = (float*)d_out;                              // [B,SQ,DH]
    float* weights  = (float*)d_out + (size_t)NB * SQ * DH;       // [B,SQ,SK]

    // 1) ||k||^2
    ksq_kernel<<<(NB * SK * 32 + 255) / 256, 256>>>(K);

    // 2) logits into weights region (scratch)
    dim3 g1(SK / 128, SQ / 128, NB);
    qk_kernel<<<g1, 256>>>(Q, K, T, weights);

    // 3) in-place softmax
    softmax_kernel<<<NB * SQ, 256>>>(weights);

    // 4) attended = weights @ V
    dim3 g2(DH / 128, SQ / 128, NB);
    pv_kernel<<<g2, 256>>>(weights, V, attended);
}

// round 3
// speedup vs baseline: 2.9706x; 2.9706x over previous
#include <cuda_runtime.h>
#include <cuda_bf16.h>
#include <cstdint>

#define NB 8
#define SQ 2048
#define SK 2048
#define DH 512

#define KTILE 64
#define TILE_B (128 * KTILE * 2)                 // 16384 bytes per operand tile
#define SMEM_TILES 1024
#define SMEM_TOTAL (SMEM_TILES + 2 * 4 * TILE_B) // 132096 bytes

// tcgen05 is an arch-accelerated ('a') feature: only emit it in compilation
// passes that target sm_103a/sm_100a (or arch/family-specific variants).
#if defined(__CUDA_ARCH_FEAT_SM103_ALL) || defined(__CUDA_ARCH_FEAT_SM100_ALL) || \
    defined(__CUDA_ARCH_FEAT_SM101_ALL) ||                                        \
    (defined(__CUDA_ARCH_SPECIFIC__) && (__CUDA_ARCH_SPECIFIC__ >= 1000)) ||      \
    (defined(__CUDA_ARCH_FAMILY_SPECIFIC__) && (__CUDA_ARCH_FAMILY_SPECIFIC__ >= 1000))
#define HAS_TCGEN05 1
#else
#define HAS_TCGEN05 0
#endif

// ------------------------- device scratch -------------------------
__device__ float g_ksq[NB * SK];
__device__ __align__(128) __nv_bfloat16 g_Qh[NB * SQ * DH];
__device__ __align__(128) __nv_bfloat16 g_Ql[NB * SQ * DH];
__device__ __align__(128) __nv_bfloat16 g_Kh[NB * SK * DH];
__device__ __align__(128) __nv_bfloat16 g_Kl[NB * SK * DH];
__device__ __align__(128) __nv_bfloat16 g_Wh[(size_t)NB * SQ * SK];
__device__ __align__(128) __nv_bfloat16 g_Wl[(size_t)NB * SQ * SK];
__device__ __align__(128) __nv_bfloat16 g_Vth[NB * DH * SK];
__device__ __align__(128) __nv_bfloat16 g_Vtl[NB * DH * SK];

// ------------------------- ptx helpers -------------------------
__device__ __forceinline__ uint32_t smem_u32(const void* p) {
    uint32_t a;
    asm("{ .reg .u64 t; cvta.to.shared.u64 t, %1; cvt.u32.u64 %0, t; }" : "=r"(a) : "l"(p));
    return a;
}
__device__ __forceinline__ uint32_t elect1() {
    uint32_t p;
    asm volatile("{\n\t.reg .pred p;\n\telect.sync _|p, 0xFFFFFFFF;\n\tselp.b32 %0,1,0,p;\n\t}" : "=r"(p));
    return p;
}
__device__ __forceinline__ void mbar_init(uint32_t addr, uint32_t cnt) {
    asm volatile("mbarrier.init.shared.b64 [%0], %1;" :: "r"(addr), "r"(cnt) : "memory");
}
__device__ __forceinline__ void mbar_wait(uint32_t mbar, uint32_t parity) {
    asm volatile(
        "{\n\t.reg .pred P;\n\t"
        "W_%=:\n\t"
        "mbarrier.try_wait.parity.acquire.cta.shared::cta.b64 P, [%0], %1, 0x989680;\n\t"
        "@P bra.uni D_%=;\n\t"
        "bra.uni W_%=;\n\t"
        "D_%=:\n\t}"
        :: "r"(mbar), "r"(parity) : "memory");
}
__device__ __forceinline__ void fence_async_shared() {
    asm volatile("fence.proxy.async.shared::cta;" ::: "memory");
}

#if HAS_TCGEN05
__device__ __forceinline__ void tmem_alloc(uint32_t smem_addr, uint32_t ncols) {
    asm volatile("tcgen05.alloc.cta_group::1.sync.aligned.shared::cta.b32 [%0], %1;"
                 :: "r"(smem_addr), "r"(ncols) : "memory");
}
__device__ __forceinline__ void tmem_dealloc(uint32_t tmem, uint32_t ncols) {
    asm volatile("tcgen05.dealloc.cta_group::1.sync.aligned.b32 %0, %1;" :: "r"(tmem), "r"(ncols));
}
__device__ __forceinline__ void tmem_relinquish() {
    asm volatile("tcgen05.relinquish_alloc_permit.cta_group::1.sync.aligned;");
}
__device__ __forceinline__ void mma_commit(uint32_t mbar) {
    asm volatile("tcgen05.commit.cta_group::1.mbarrier::arrive::one.shared::cluster.b64 [%0];"
                 :: "r"(mbar) : "memory");
}
__device__ __forceinline__ void tc_fence_after() {
    asm volatile("tcgen05.fence::after_thread_sync;" ::: "memory");
}
__device__ __forceinline__ void tc_wait_ld() {
    asm volatile("tcgen05.wait::ld.sync.aligned;" ::: "memory");
}
__device__ __forceinline__ uint64_t mk_desc(uint32_t addr) {
    // SW128, version=1 (Blackwell), SBO=64, LBO=1  (K-major, 128B rows)
    return (2ULL << 61) | (1ULL << 46) | (64ULL << 32) | (1ULL << 16) |
           ((uint64_t)(addr >> 4) & 0x3FFF);
}
__device__ __forceinline__ void mma_bf16_ss(uint32_t d, uint64_t da, uint64_t db,
                                            uint32_t idesc, uint32_t acc) {
    asm volatile(
        "{\n\t.reg .pred p;\n\t"
        "setp.ne.u32 p, %4, 0;\n\t"
        "tcgen05.mma.cta_group::1.kind::f16 [%0], %1, %2, %3, {%5, %5, %5, %5}, p;\n\t}"
        :: "r"(d), "l"(da), "l"(db), "r"(idesc), "r"(acc), "r"(0u) : "memory");
}
__device__ __forceinline__ void ldtm32(uint32_t* r, uint32_t a) {
    asm volatile(
        "tcgen05.ld.sync.aligned.32x32b.x32.b32 "
        "{%0,%1,%2,%3,%4,%5,%6,%7,%8,%9,%10,%11,%12,%13,%14,%15,"
        "%16,%17,%18,%19,%20,%21,%22,%23,%24,%25,%26,%27,%28,%29,%30,%31}, [%32];"
        : "=r"(r[0]), "=r"(r[1]), "=r"(r[2]), "=r"(r[3]), "=r"(r[4]), "=r"(r[5]), "=r"(r[6]), "=r"(r[7]),
          "=r"(r[8]), "=r"(r[9]), "=r"(r[10]), "=r"(r[11]), "=r"(r[12]), "=r"(r[13]), "=r"(r[14]), "=r"(r[15]),
          "=r"(r[16]), "=r"(r[17]), "=r"(r[18]), "=r"(r[19]), "=r"(r[20]), "=r"(r[21]), "=r"(r[22]), "=r"(r[23]),
          "=r"(r[24]), "=r"(r[25]), "=r"(r[26]), "=r"(r[27]), "=r"(r[28]), "=r"(r[29]), "=r"(r[30]), "=r"(r[31])
        : "r"(a));
}
#endif // HAS_TCGEN05

// idesc: F32 accum, BF16 a/b, M=128, N=128
#define GEMM_IDESC ((1u << 4) | (1u << 7) | (1u << 10) | (16u << 17) | (8u << 24))

// ---------------------------------------------------------------------------
// k_sq (fp32, full precision)
// ---------------------------------------------------------------------------
__global__ __launch_bounds__(256) void ksq_kernel(const float* __restrict__ K) {
    int gw = (blockIdx.x * blockDim.x + threadIdx.x) >> 5;
    int lane = threadIdx.x & 31;
    if (gw >= NB * SK) return;
    const float* row = K + (size_t)gw * DH;
    float s = 0.f;
    #pragma unroll
    for (int i = lane * 4; i < DH; i += 128) {
        float4 v = *(const float4*)(row + i);
        s = fmaf(v.x, v.x, s); s = fmaf(v.y, v.y, s);
        s = fmaf(v.z, v.z, s); s = fmaf(v.w, v.w, s);
    }
    #pragma unroll
    for (int o = 16; o > 0; o >>= 1) s += __shfl_xor_sync(0xffffffffu, s, o);
    if (lane == 0) g_ksq[gw] = s;
}

// ---------------------------------------------------------------------------
// fp32 -> (hi, lo) bf16 split
// ---------------------------------------------------------------------------
__global__ __launch_bounds__(256) void split_kernel(const float* __restrict__ X,
                                                    __nv_bfloat16* __restrict__ Xh,
                                                    __nv_bfloat16* __restrict__ Xl,
                                                    int n4) {
    int i = blockIdx.x * blockDim.x + threadIdx.x;
    if (i >= n4) return;
    float4 v = ((const float4*)X)[i];
    __nv_bfloat16 h0 = __float2bfloat16(v.x), h1 = __float2bfloat16(v.y);
    __nv_bfloat16 h2 = __float2bfloat16(v.z), h3 = __float2bfloat16(v.w);
    __nv_bfloat16 l0 = __float2bfloat16(v.x - __bfloat162float(h0));
    __nv_bfloat16 l1 = __float2bfloat16(v.y - __bfloat162float(h1));
    __nv_bfloat16 l2 = __float2bfloat16(v.z - __bfloat162float(h2));
    __nv_bfloat16 l3 = __float2bfloat16(v.w - __bfloat162float(h3));
    ((__nv_bfloat162*)Xh)[2 * i]     = __nv_bfloat162(h0, h1);
    ((__nv_bfloat162*)Xh)[2 * i + 1] = __nv_bfloat162(h2, h3);
    ((__nv_bfloat162*)Xl)[2 * i]     = __nv_bfloat162(l0, l1);
    ((__nv_bfloat162*)Xl)[2 * i + 1] = __nv_bfloat162(l2, l3);
}

// ---------------------------------------------------------------------------
// V transpose + split:  Vt[b][d][k] = V[b][k][d]  (hi/lo bf16)
// ---------------------------------------------------------------------------
__global__ __launch_bounds__(256) void vsplit_kernel(const float* __restrict__ V) {
    __shared__ float t[32][33];
    const int b = blockIdx.z;
    const int d0 = blockIdx.x * 32, k0 = blockIdx.y * 32;
    const float* Vb = V + (size_t)b * SK * DH;
    const int tx = threadIdx.x, ty = threadIdx.y; // 32 x 8
    #pragma unroll
    for (int j = 0; j < 4; j++)
        t[ty + j * 8][tx] = Vb[(size_t)(k0 + ty + j * 8) * DH + d0 + tx];
    __syncthreads();
    #pragma unroll
    for (int j = 0; j < 4; j++) {
        float x = t[tx][ty + j * 8];
        __nv_bfloat16 h = __float2bfloat16(x);
        __nv_bfloat16 l = __float2bfloat16(x - __bfloat162float(h));
        size_t o = (size_t)b * DH * SK + (size_t)(d0 + ty + j * 8) * SK + k0 + tx;
        g_Vth[o] = h;
        g_Vtl[o] = l;
    }
}

// ---------------------------------------------------------------------------
// GEMM:  D[m][n] = sum_k A[m][k]*B[n][k]   (fp32 accum)
// tcgen05 split-bf16 path when available; fp32 FFMA fallback otherwise.
// Af/Bf are the fp32 originals used only by the fallback path.
//   QK fallback: A=Q [m][k] stride KDIM, B=K [n][k] stride KDIM (NT)
//   PV fallback: A=W [m][k] stride KDIM, B=V [k][n] stride DH  (NN)
// ---------------------------------------------------------------------------
template <int KDIM, int LDOUT, int BROWS, bool IS_QK>
__global__ __launch_bounds__(256, 1) void gemm5_kernel(
    const __nv_bfloat16* __restrict__ Ah, const __nv_bfloat16* __restrict__ Al,
    const __nv_bfloat16* __restrict__ Bh, const __nv_bfloat16* __restrict__ Bl,
    const float* __restrict__ Af, const float* __restrict__ Bf,
    float* __restrict__ Out, const float* __restrict__ temp) {
    extern __shared__ __align__(1024) char smem[];

    const int tid = threadIdx.x;
    const int wid = tid >> 5, lid = tid & 31;
    const int b = blockIdx.z;
    const int m0 = blockIdx.y * 128, n0 = blockIdx.x * 128;

#if HAS_TCGEN05
    const uint32_t sbase = smem_u32(smem);
    const __nv_bfloat16* pA[2] = {Ah + (size_t)b * SQ * KDIM, Al + (size_t)b * SQ * KDIM};
    const __nv_bfloat16* pB[2] = {Bh + (size_t)b * BROWS * KDIM, Bl + (size_t)b * BROWS * KDIM};

    if (wid == 0) {
        tmem_alloc(sbase, 128);
        tmem_relinquish();
    }
    if (tid == 0) {
        mbar_init(sbase + 8, 1);
        mbar_init(sbase + 16, 1);
    }
    __syncthreads();
    uint32_t tmem;
    asm volatile("ld.shared.b32 %0, [%1];" : "=r"(tmem) : "r"(sbase));

    constexpr int NSTAGE = KDIM / KTILE;
    int ph0 = 0, ph1 = 0;

    for (int s = 0; s < NSTAGE; s++) {
        const int buf = s & 1;
        const uint32_t mbar = sbase + 8 + buf * 8;
        if (s >= 2) {
            if (buf == 0) { mbar_wait(mbar, ph0); ph0 ^= 1; }
            else          { mbar_wait(mbar, ph1); ph1 ^= 1; }
        }
        const int k0 = s * KTILE;
        char* bufp = smem + SMEM_TILES + buf * (4 * TILE_B);
        #pragma unroll
        for (int half = 0; half < 2; half++) {
            #pragma unroll
            for (int hl = 0; hl < 2; hl++) {
                const __nv_bfloat16* src = (half == 0) ? pA[hl] : pB[hl];
                const int rbase = (half == 0) ? m0 : n0;
                char* dstp = bufp + (half * 2 + hl) * TILE_B;
                #pragma unroll
                for (int i = 0; i < 4; i++) {
                    int idx = tid + i * 256;
                    int row = idx >> 3, c8 = idx & 7;
                    uint4 v = *(const uint4*)(src + (size_t)(rbase + row) * KDIM + k0 + c8 * 8);
                    uint32_t off = row * 128 + c8 * 16;
                    off ^= (off >> 3) & 0x70;
                    *(uint4*)(dstp + off) = v;
                }
            }
        }
        __syncthreads();
        if (wid == 0) {
            fence_async_shared();
            if (elect1()) {
                uint32_t base = sbase + SMEM_TILES + buf * (4 * TILE_B);
                uint64_t dAh = mk_desc(base);
                uint64_t dAl = mk_desc(base + TILE_B);
                uint64_t dBh = mk_desc(base + 2 * TILE_B);
                uint64_t dBl = mk_desc(base + 3 * TILE_B);
                #pragma unroll
                for (int ks = 0; ks < KTILE / 16; ks++) {
                    uint32_t acc0 = (s == 0 && ks == 0) ? 0u : 1u;
                    mma_bf16_ss(tmem, dAh + ks * 2, dBh + ks * 2, GEMM_IDESC, acc0);
                    mma_bf16_ss(tmem, dAh + ks * 2, dBl + ks * 2, GEMM_IDESC, 1u);
                    mma_bf16_ss(tmem, dAl + ks * 2, dBh + ks * 2, GEMM_IDESC, 1u);
                }
                mma_commit(mbar);
            }
        }
    }

    mbar_wait(sbase + 8, ph0);
    mbar_wait(sbase + 16, ph1);
    tc_fence_after();

    if (wid < 4) {
        const int m = m0 + wid * 32 + lid;
        float invT = 1.0f;
        if (IS_QK) invT = 1.0f / temp[0];
        #pragma unroll
        for (int cb = 0; cb < 128; cb += 32) {
            uint32_t r[32];
            ldtm32(r, tmem + cb);
            tc_wait_ld();
            float* op = Out + (size_t)b * SQ * LDOUT + (size_t)m * LDOUT + n0 + cb;
            if (IS_QK) {
                const float* kq = g_ksq + b * SK + n0 + cb;
                #pragma unroll
                for (int c = 0; c < 32; c += 4) {
                    float4 o;
                    o.x = (2.f * __uint_as_float(r[c + 0]) - kq[c + 0]) * invT;
                    o.y = (2.f * __uint_as_float(r[c + 1]) - kq[c + 1]) * invT;
                    o.z = (2.f * __uint_as_float(r[c + 2]) - kq[c + 2]) * invT;
                    o.w = (2.f * __uint_as_float(r[c + 3]) - kq[c + 3]) * invT;
                    *(float4*)(op + c) = o;
                }
            } else {
                #pragma unroll
                for (int c = 0; c < 32; c += 4) {
                    float4 o;
                    o.x = __uint_as_float(r[c + 0]);
                    o.y = __uint_as_float(r[c + 1]);
                    o.z = __uint_as_float(r[c + 2]);
                    o.w = __uint_as_float(r[c + 3]);
                    *(float4*)(op + c) = o;
                }
            }
        }
    }
    __syncthreads();
    if (wid == 0) tmem_dealloc(tmem, 128);

#else  // ---------------- fp32 FFMA fallback ----------------
    (void)Ah; (void)Al; (void)Bh; (void)Bl;
    float (*As)[132] = (float (*)[132])smem;
    float (*Bs)[132] = (float (*)[132])(smem + 16 * 132 * sizeof(float));

    const float* Ab = Af + (size_t)b * SQ * KDIM;
    const float* Bb = IS_QK ? (Bf + (size_t)b * BROWS * KDIM)
                            : (Bf + (size_t)b * BROWS * KDIM); // same base math
    float* Ob = Out + (size_t)b * SQ * LDOUT;

    const int lr = tid >> 2;
    const int lc = (tid & 3) << 2;
    const int br = tid >> 5;
    const int bc = (tid & 31) << 2;
    const int tm = (tid >> 4) << 3;
    const int tn = (tid & 15) << 3;

    float acc[8][8];
    #pragma unroll
    for (int i = 0; i < 8; i++)
        #pragma unroll
        for (int j = 0; j < 8; j++) acc[i][j] = 0.f;

    for (int k0 = 0; k0 < KDIM; k0 += 16) {
        #pragma unroll
        for (int i = 0; i < 2; i++) {
            int row = lr + i * 64;
            float4 v = *(const float4*)(Ab + (size_t)(m0 + row) * KDIM + k0 + lc);
            As[lc + 0][row] = v.x; As[lc + 1][row] = v.y;
            As[lc + 2][row] = v.z; As[lc + 3][row] = v.w;
        }
        if (IS_QK) {
            #pragma unroll
            for (int i = 0; i < 2; i++) {
                int row = lr + i * 64;
                float4 w = *(const float4*)(Bb + (size_t)(n0 + row) * KDIM + k0 + lc);
                Bs[lc + 0][row] = w.x; Bs[lc + 1][row] = w.y;
                Bs[lc + 2][row] = w.z; Bs[lc + 3][row] = w.w;
            }
        } else {
            #pragma unroll
            for (int i = 0; i < 2; i++) {
                int row = br + i * 8;
                float4 v = *(const float4*)(Bb + (size_t)(k0 + row) * DH + n0 + bc);
                *(float4*)&Bs[row][bc] = v;
            }
        }
        __syncthreads();
        #pragma unroll
        for (int kk = 0; kk < 16; kk++) {
            float a[8], bb[8];
            #pragma unroll
            for (int i = 0; i < 8; i++) a[i] = As[kk][tm + i];
            #pragma unroll
            for (int j = 0; j < 8; j++) bb[j] = Bs[kk][tn + j];
            #pragma unroll
            for (int i = 0; i < 8; i++)
                #pragma unroll
                for (int j = 0; j < 8; j++)
                    acc[i][j] = fmaf(a[i], bb[j], acc[i][j]);
        }
        __syncthreads();
    }

    if (IS_QK) {
        const float invT = 1.0f / temp[0];
        float kq[8];
        #pragma unroll
        for (int j = 0; j < 8; j++) kq[j] = g_ksq[b * SK + n0 + tn + j];
        #pragma unroll
        for (int i = 0; i < 8; i++) {
            float* op = Ob + (size_t)(m0 + tm + i) * LDOUT + n0 + tn;
            #pragma unroll
            for (int j = 0; j < 8; j++)
                op[j] = (2.0f * acc[i][j] - kq[j]) * invT;
        }
    } else {
        #pragma unroll
        for (int i = 0; i < 8; i++) {
            float* op = Ob + (size_t)(m0 + tm + i) * LDOUT + n0 + tn;
            *(float4*)(op + 0) = make_float4(acc[i][0], acc[i][1], acc[i][2], acc[i][3]);
            *(float4*)(op + 4) = make_float4(acc[i][4], acc[i][5], acc[i][6], acc[i][7]);
        }
    }
#endif
}

// ---------------------------------------------------------------------------
// softmax (in-place fp32) + bf16 hi/lo split of the weights
// ---------------------------------------------------------------------------
__global__ __launch_bounds__(256) void softmax_kernel(float* __restrict__ W) {
    const int row = blockIdx.x;
    float* r = W + (size_t)row * SK;
    const int tid = threadIdx.x;

    float vals[8];
    float m = -3.0e38f;
    #pragma unroll
    for (int i = 0; i < 8; i++) {
        vals[i] = r[tid + i * 256];
        m = fmaxf(m, vals[i]);
    }

    __shared__ float red[8];
    #pragma unroll
    for (int o = 16; o > 0; o >>= 1) m = fmaxf(m, __shfl_xor_sync(0xffffffffu, m, o));
    if ((tid & 31) == 0) red[tid >> 5] = m;
    __syncthreads();
    m = red[0];
    #pragma unroll
    for (int w = 1; w < 8; w++) m = fmaxf(m, red[w]);
    __syncthreads();

    float s = 0.f;
    #pragma unroll
    for (int i = 0; i < 8; i++) {
        vals[i] = expf(vals[i] - m);
        s += vals[i];
    }
    #pragma unroll
    for (int o = 16; o > 0; o >>= 1) s += __shfl_xor_sync(0xffffffffu, s, o);
    if ((tid & 31) == 0) red[tid >> 5] = s;
    __syncthreads();
    s = red[0];
    #pragma unroll
    for (int w = 1; w < 8; w++) s += red[w];

    const float inv = 1.0f / s;
    const size_t base = (size_t)row * SK;
    #pragma unroll
    for (int i = 0; i < 8; i++) {
        float v = vals[i] * inv;
        int idx = tid + i * 256;
        r[idx] = v;
        __nv_bfloat16 h = __float2bfloat16(v);
        g_Wh[base + idx] = h;
        g_Wl[base + idx] = __float2bfloat16(v - __bfloat162float(h));
    }
}

// ---------------------------------------------------------------------------
extern "C" void kernel_launch(void* const* d_in, const int* in_sizes, int n_in,
                              void* d_out, int out_size) {
    const float* Q = (const float*)d_in[0];
    const float* K = (const float*)d_in[1];
    const float* V = (const float*)d_in[2];
    const float* T = (const float*)d_in[3];

    float* attended = (float*)d_out;                        // [B,SQ,DH]
    float* weights  = (float*)d_out + (size_t)NB * SQ * DH; // [B,SQ,SK]

    void *qh, *ql, *kh, *kl, *wh, *wl, *vth, *vtl;
    cudaGetSymbolAddress(&qh, g_Qh);
    cudaGetSymbolAddress(&ql, g_Ql);
    cudaGetSymbolAddress(&kh, g_Kh);
    cudaGetSymbolAddress(&kl, g_Kl);
    cudaGetSymbolAddress(&wh, g_Wh);
    cudaGetSymbolAddress(&wl, g_Wl);
    cudaGetSymbolAddress(&vth, g_Vth);
    cudaGetSymbolAddress(&vtl, g_Vtl);

    cudaFuncSetAttribute((const void*)gemm5_kernel<512, SK, SK, true>,
                         cudaFuncAttributeMaxDynamicSharedMemorySize, SMEM_TOTAL);
    cudaFuncSetAttribute((const void*)gemm5_kernel<2048, DH, DH, false>,
                         cudaFuncAttributeMaxDynamicSharedMemorySize, SMEM_TOTAL);

    // 1) precision splits + ksq + V transpose/split
    const int n4 = NB * SQ * DH / 4;
    split_kernel<<<n4 / 256, 256>>>(Q, (__nv_bfloat16*)qh, (__nv_bfloat16*)ql, n4);
    split_kernel<<<n4 / 256, 256>>>(K, (__nv_bfloat16*)kh, (__nv_bfloat16*)kl, n4);
    ksq_kernel<<<NB * SK * 32 / 256, 256>>>(K);
    vsplit_kernel<<<dim3(DH / 32, SK / 32, NB), dim3(32, 8)>>>(V);

    // 2) logits = (2 q.k - ksq)/T  into weights region (tensor cores)
    gemm5_kernel<512, SK, SK, true><<<dim3(SK / 128, SQ / 128, NB), 256, SMEM_TOTAL>>>(
        (__nv_bfloat16*)qh, (__nv_bfloat16*)ql, (__nv_bfloat16*)kh, (__nv_bfloat16*)kl,
        Q, K, weights, T);

    // 3) softmax in-place + split to bf16 hi/lo
    softmax_kernel<<<NB * SQ, 256>>>(weights);

    // 4) attended = W @ V  (tensor cores)
    gemm5_kernel<2048, DH, DH, false><<<dim3(DH / 128, SQ / 128, NB), 256, SMEM_TOTAL>>>(
        (__nv_bfloat16*)wh, (__nv_bfloat16*)wl, (__nv_bfloat16*)vth, (__nv_bfloat16*)vtl,
        weights, V, attended, nullptr);
}